// round 8
// baseline (speedup 1.0000x reference)
#include <cuda_runtime.h>
#include <math.h>

#define D  4096
#define K2 8192
#define KS 32          // split-K chunks
#define KC (K2 / KS)   // 256 rows per chunk
#define NB 8           // gemv n-chunks of 512 cols -> grid (8,32,4) = 1024 blocks

#define FB 32          // finish kernel blocks (8 per gate)
#define FT 512         // finish kernel threads (1 element per thread)
#define NEG_INF_BITS 0xFF800000u

// ---------------- scratch (no device allocation allowed) ----------------
__device__ float    g_partial[4 * KS * D];   // split-K partial sums (2 MB, L2-resident)
__device__ float    g_qa[4 * D];             // quantized gate activations (f, i, c, o)
__device__ unsigned g_ctr[7];                // round counters (zero-init)
__device__ unsigned g_accmax[4];             // max|x@w| per gate        (init 0)
__device__ unsigned g_bmax[4];               // max|b| per gate          (init 0)
__device__ unsigned g_ymax[4]  = {NEG_INF_BITS, NEG_INF_BITS, NEG_INF_BITS, NEG_INF_BITS};
__device__ unsigned g_yneg[4]  = {NEG_INF_BITS, NEG_INF_BITS, NEG_INF_BITS, NEG_INF_BITS};
__device__ unsigned g_memmax, g_cfmax, g_cnmax, g_hmax;   // tail maxes (init 0)

// ---------------- helpers ----------------
__device__ __forceinline__ float mkscale(float maxabs) {
    return (maxabs > 0.0f) ? (maxabs / 127.0f) : 1.0f;
}

__device__ __forceinline__ float qvalr(float x, float scale, float rscale) {
    float r = rintf(x * rscale);
    r = fminf(fmaxf(r, -127.0f), 127.0f);
    return r * scale;
}

__device__ __forceinline__ float sigm(float x) {
    return __fdividef(1.0f, 1.0f + __expf(-x));
}

// order-independent signed float atomic max (slot init = -INF bits)
__device__ __forceinline__ void atomicMaxFloatSigned(unsigned* addr, float v) {
    if (v >= 0.0f) atomicMax((int*)addr, __float_as_int(v));
    else           atomicMin(addr, __float_as_uint(v));
}
// nonnegative float atomic max (slot init = 0)
__device__ __forceinline__ void atomicMaxFloatU(unsigned* addr, float v) {
    atomicMax(addr, __float_as_uint(v));
}
__device__ __forceinline__ float slotF(const unsigned* a) {
    return __uint_as_float(*(volatile const unsigned*)a);
}

// Block-wide max (signed-safe).
__device__ __forceinline__ float blockMax(float v) {
    __shared__ float s[32];
    const unsigned full = 0xffffffffu;
    #pragma unroll
    for (int o = 16; o; o >>= 1) v = fmaxf(v, __shfl_xor_sync(full, v, o));
    int lane = threadIdx.x & 31, w = threadIdx.x >> 5;
    int nw = (blockDim.x + 31) >> 5;
    if (lane == 0) s[w] = v;
    __syncthreads();
    if (w == 0) {
        float r = (lane < nw) ? s[lane] : -INFINITY;
        #pragma unroll
        for (int o = 16; o; o >>= 1) r = fmaxf(r, __shfl_xor_sync(full, r, o));
        if (lane == 0) s[0] = r;
    }
    __syncthreads();
    float out = s[0];
    __syncthreads();
    return out;
}

// Two block maxes sharing one barrier set.
__device__ __forceinline__ float2 blockMax2(float a, float b) {
    __shared__ float sa[32], sb[32];
    const unsigned full = 0xffffffffu;
    #pragma unroll
    for (int o = 16; o; o >>= 1) {
        a = fmaxf(a, __shfl_xor_sync(full, a, o));
        b = fmaxf(b, __shfl_xor_sync(full, b, o));
    }
    int lane = threadIdx.x & 31, w = threadIdx.x >> 5;
    int nw = (blockDim.x + 31) >> 5;
    if (lane == 0) { sa[w] = a; sb[w] = b; }
    __syncthreads();
    if (w == 0) {
        float ra = (lane < nw) ? sa[lane] : -INFINITY;
        float rb = (lane < nw) ? sb[lane] : -INFINITY;
        #pragma unroll
        for (int o = 16; o; o >>= 1) {
            ra = fmaxf(ra, __shfl_xor_sync(full, ra, o));
            rb = fmaxf(rb, __shfl_xor_sync(full, rb, o));
        }
        if (lane == 0) { sa[0] = ra; sb[0] = rb; }
    }
    __syncthreads();
    float2 out = make_float2(sa[0], sb[0]);
    __syncthreads();
    return out;
}

// device-wide barrier: arrive + spin until `target` blocks arrived.
__device__ __forceinline__ void gsync(int k, unsigned target) {
    __threadfence();
    __syncthreads();
    if (threadIdx.x == 0) {
        atomicAdd(&g_ctr[k], 1u);
        while (*(volatile unsigned*)&g_ctr[k] < target) {}
    }
    __syncthreads();
}
// arrive without waiting (for blocks that exit)
__device__ __forceinline__ void garrive(int k) {
    __threadfence();
    __syncthreads();
    if (threadIdx.x == 0) atomicAdd(&g_ctr[k], 1u);
}

// ---------------- kernel 1: fused concat-quant + split-K GEMV (HBM-bound) ----------------
// Measured ~77us (~7 TB/s) — at the HBM practical ceiling; DO NOT reshape.
__global__ void __launch_bounds__(256) gemv_kernel(
    const float* __restrict__ x,  const float* __restrict__ h,
    const float* __restrict__ Wf, const float* __restrict__ Wi,
    const float* __restrict__ Wc, const float* __restrict__ Wo)
{
    __shared__ float xs[KC];
    const int g  = blockIdx.z;
    const int kc = blockIdx.y;
    const int n0 = blockIdx.x * 512 + threadIdx.x * 2;
    const int k0 = kc * KC;

    const float* W = (g == 0) ? Wf : (g == 1) ? Wi : (g == 2) ? Wc : Wo;

    float lm = 0.0f;
    #pragma unroll
    for (int j = 0; j < K2 / 256; j++) {
        int i = threadIdx.x + j * 256;
        float v = (i < D) ? h[i] : x[i - D];
        lm = fmaxf(lm, fabsf(v));
    }
    float scale = mkscale(blockMax(lm));
    float rs = 1.0f / scale;

    {
        int gi = k0 + threadIdx.x;
        float v = (gi < D) ? h[gi] : x[gi - D];
        xs[threadIdx.x] = qvalr(v, scale, rs);
    }
    __syncthreads();

    const float2* p = reinterpret_cast<const float2*>(W + (size_t)k0 * D) + (n0 >> 1);
    const int rowstride = D / 2;

    float2 acc = make_float2(0.f, 0.f);
    #pragma unroll 8
    for (int i = 0; i < KC; i++) {
        float2 w = __ldcs(p + (size_t)i * rowstride);
        float  xv = xs[i];
        acc.x = fmaf(xv, w.x, acc.x);
        acc.y = fmaf(xv, w.y, acc.y);
    }
    *reinterpret_cast<float2*>(&g_partial[(size_t)(g * KS + kc) * D + n0]) = acc;
}

// ---------------- kernel 2: finish — reduce + quant chain + tail, 32 blocks ----------------
// block b: gate g = b>>3, slice = b&7; thread owns element idx = slice*512+tid of gate g.
// 6 device-wide rounds; rounds 0-2 use all 32 blocks, rounds 3-5 the 8 gate-0 blocks.
__global__ void __launch_bounds__(FT, 1)
finish_kernel(const float* __restrict__ bf, const float* __restrict__ bi,
              const float* __restrict__ bc, const float* __restrict__ bo,
              const float* __restrict__ c_in, float* __restrict__ out)
{
    const int g   = blockIdx.x >> 3;
    const int idx = (blockIdx.x & 7) * FT + threadIdx.x;   // 0..4095
    const float* b = (g == 0) ? bf : (g == 1) ? bi : (g == 2) ? bc : bo;

    const float bv = b[idx];
    const float cv = c_in[idx];      // only used by gate-0 blocks; load cost hidden

    // --- split-K reduce: 32 scalar L2 loads, 8 independent chains ---
    const float* pb = g_partial + (size_t)g * KS * D + idx;
    float a0=0.f,a1=0.f,a2=0.f,a3=0.f,a4=0.f,a5=0.f,a6=0.f,a7=0.f;
    #pragma unroll
    for (int ks = 0; ks < KS; ks += 8) {
        a0 += pb[(size_t)(ks+0) * D]; a1 += pb[(size_t)(ks+1) * D];
        a2 += pb[(size_t)(ks+2) * D]; a3 += pb[(size_t)(ks+3) * D];
        a4 += pb[(size_t)(ks+4) * D]; a5 += pb[(size_t)(ks+5) * D];
        a6 += pb[(size_t)(ks+6) * D]; a7 += pb[(size_t)(ks+7) * D];
    }
    float acc = ((a0+a1)+(a2+a3)) + ((a4+a5)+(a6+a7));

    // --- round 0: per-gate max|acc|, max|b| ---
    float2 m01 = blockMax2(fabsf(acc), fabsf(bv));
    if (threadIdx.x == 0) {
        atomicMaxFloatU(&g_accmax[g], m01.x);
        atomicMaxFloatU(&g_bmax[g],  m01.y);
    }
    gsync(0, FB);
    float sm = mkscale(slotF(&g_accmax[g])), rsm = 1.0f / sm;
    float sb = mkscale(slotF(&g_bmax[g])),  rsb = 1.0f / sb;

    // --- round 1: y = Q(x@w)+Q(b); per-gate signed max/min ---
    float y = qvalr(acc, sm, rsm) + qvalr(bv, sb, rsb);
    float2 ymm = blockMax2(y, -y);
    if (threadIdx.x == 0) {
        atomicMaxFloatSigned(&g_ymax[g], ymm.x);
        atomicMaxFloatSigned(&g_yneg[g], ymm.y);
    }
    gsync(1, FB);
    float ymax = slotF(&g_ymax[g]);
    float ynab = fmaxf(ymax, slotF(&g_yneg[g]));         // max|y|
    float sy   = mkscale(ynab), rsy = 1.0f / sy;

    // analytic activation scale (monotone functions -> evaluate at argmax)
    float sa = (g == 2) ? mkscale(tanhf(qvalr(ynab, sy, rsy)))
                        : mkscale(sigm(qvalr(ymax, sy, rsy)));
    float rsa = 1.0f / sa;

    float yq = qvalr(y, sy, rsy);
    float av = (g == 2) ? tanhf(yq) : sigm(yq);
    float qa = qvalr(av, sa, rsa);
    g_qa[g * D + idx] = qa;

    // --- round 2: qa handshake; non-gate-0 blocks exit ---
    if (g != 0) { garrive(2); return; }
    gsync(2, FB);

    // --- tail on 8 blocks / 4096 threads (1 element each) ---
    float zf = qa;                                       // own gate-0 value
    float zi = __ldcg(&g_qa[1 * D + idx]);
    float z  = __ldcg(&g_qa[2 * D + idx]);
    float zo = __ldcg(&g_qa[3 * D + idx]);

    float mem = z * zi;
    float cf  = cv * zf;

    float2 mc = blockMax2(fabsf(mem), fabsf(cf));
    if (threadIdx.x == 0) {
        atomicMaxFloatU(&g_memmax, mc.x);
        atomicMaxFloatU(&g_cfmax,  mc.y);
    }
    gsync(3, NB);
    float s_mem = mkscale(slotF(&g_memmax)), r_mem = 1.0f / s_mem;
    float s_cf  = mkscale(slotF(&g_cfmax)),  r_cf  = 1.0f / s_cf;

    float cn = qvalr(cf, s_cf, r_cf) + qvalr(mem, s_mem, r_mem);   // Q(c*zf)+Q(z*zi)
    float cm = blockMax(fabsf(cn));
    if (threadIdx.x == 0) atomicMaxFloatU(&g_cnmax, cm);
    gsync(4, NB);
    float cnmax = slotF(&g_cnmax);
    float s_cn  = mkscale(cnmax), r_cn = 1.0f / s_cn;
    float s_t   = mkscale(tanhf(qvalr(cnmax, s_cn, r_cn)));        // analytic tanh scale
    float r_t   = 1.0f / s_t;

    float cq = qvalr(cn, s_cn, r_cn);                    // c_new
    float tq = qvalr(tanhf(cq), s_t, r_t);               // Q(tanh(c_new))
    float hv = zo * tq;

    float hm = blockMax(fabsf(hv));
    if (threadIdx.x == 0) atomicMaxFloatU(&g_hmax, hm);
    gsync(5, NB);
    float s_h = mkscale(slotF(&g_hmax)), r_h = 1.0f / s_h;

    out[idx] = qvalr(hv, s_h, r_h);

    // --- final ticket: last block resets all state for the next graph replay ---
    __threadfence();
    __syncthreads();
    if (threadIdx.x == 0) {
        unsigned tk = atomicAdd(&g_ctr[6], 1u);
        if (tk == NB - 1) {
            #pragma unroll
            for (int k = 0; k < 7; k++) g_ctr[k] = 0u;
            #pragma unroll
            for (int k = 0; k < 4; k++) {
                g_accmax[k] = 0u; g_bmax[k] = 0u;
                g_ymax[k] = NEG_INF_BITS; g_yneg[k] = NEG_INF_BITS;
            }
            g_memmax = 0u; g_cfmax = 0u; g_cnmax = 0u; g_hmax = 0u;
            __threadfence();
        }
    }
}

// ---------------- launch ----------------
extern "C" void kernel_launch(void* const* d_in, const int* in_sizes, int n_in,
                              void* d_out, int out_size)
{
    const float* x  = (const float*)d_in[0];
    const float* c  = (const float*)d_in[1];
    const float* h  = (const float*)d_in[2];
    const float* Wf = (const float*)d_in[3];
    const float* bf = (const float*)d_in[4];
    const float* Wi = (const float*)d_in[5];
    const float* bi = (const float*)d_in[6];
    const float* Wc = (const float*)d_in[7];
    const float* bc = (const float*)d_in[8];
    const float* Wo = (const float*)d_in[9];
    const float* bo = (const float*)d_in[10];

    dim3 gridB(NB, KS, 4);                     // (8, 32, 4) = 1024 blocks
    gemv_kernel<<<gridB, 256>>>(x, h, Wf, Wi, Wc, Wo);

    finish_kernel<<<FB, FT>>>(bf, bi, bc, bo, c, (float*)d_out);
}